// round 16
// baseline (speedup 1.0000x reference)
#include <cuda_runtime.h>
#include <cstdint>

#define DIMV   512
#define NTOK   256
#define NKEEP  128
#define HID    102
#define KP     51
#define OUTROWS 52
#define NB     512
#define HST    106   // H row stride: conflict-free GEMM2 row reads; even -> ull-aligned w

typedef unsigned long long ull;

__device__ int   g_selidx[NB * NKEEP];
__device__ float g_mu[NB * NKEEP];
__device__ float g_rinv[NB * NKEEP];

__device__ __forceinline__ ull ffma2(ull a, ull b, ull c) {
    ull d; asm("fma.rn.f32x2 %0, %1, %2, %3;" : "=l"(d) : "l"(a), "l"(b), "l"(c)); return d;
}
__device__ __forceinline__ ull pack2(float x, float y) {
    ull d; asm("mov.b64 %0, {%1, %2};" : "=l"(d) : "f"(x), "f"(y)); return d;
}
__device__ __forceinline__ float2 unpack2(ull v) {
    float2 r; asm("mov.b64 {%0, %1}, %2;" : "=f"(r.x), "=f"(r.y) : "l"(v)); return r;
}
__device__ __forceinline__ float gelu_exact(float v) {
    return 0.5f * v * (1.0f + erff(v * 0.70710678118654752f));
}
__device__ __forceinline__ uint32_t smem_u32(const void* p) {
    uint32_t a; asm("{ .reg .u64 t; cvta.to.shared.u64 t, %1; cvt.u32.u64 %0, t; }" : "=r"(a) : "l"(p)); return a;
}
#define CP_ASYNC8(dst, src) \
    asm volatile("cp.async.ca.shared.global [%0], [%1], 8;" :: "r"(dst), "l"(src) : "memory")
#define CP_COMMIT() asm volatile("cp.async.commit_group;" ::: "memory")
#define CP_WAIT0()  asm volatile("cp.async.wait_group 0;" ::: "memory")

// =====================================================================
// K12: stats + scores + partition + non-kept softmax + extra output row
// =====================================================================
__global__ __launch_bounds__(256)
void k12_select(const float* __restrict__ x, const float* __restrict__ ca,
                float* __restrict__ out)
{
    __shared__ float scratch[8 * 512];
    __shared__ float glo[512];
    __shared__ float rowsum[256];
    __shared__ float rowsumsq[256];
    __shared__ float score[256];
    __shared__ float nscore[128];
    __shared__ float nw[128];
    __shared__ int   nonidx[128];
    __shared__ float red[8];
    __shared__ float ssq;

    const int b = blockIdx.x, tid = threadIdx.x, warp = tid >> 5, lane = tid & 31;
    const float* __restrict__ xb = x + (size_t)b * NTOK * DIMV;
    float* __restrict__ ob = out + (size_t)b * OUTROWS * DIMV;

    float4 cs0 = make_float4(0,0,0,0), cs1 = cs0, cs2 = cs0, cs3 = cs0;
    #pragma unroll 1
    for (int r = 0; r < 32; r++) {
        const int t = warp * 32 + r;
        const float4* row = reinterpret_cast<const float4*>(xb + t * DIMV);
        float4 v0 = row[lane], v1 = row[lane + 32], v2 = row[lane + 64], v3 = row[lane + 96];
        float rs = v0.x+v0.y+v0.z+v0.w + v1.x+v1.y+v1.z+v1.w
                 + v2.x+v2.y+v2.z+v2.w + v3.x+v3.y+v3.z+v3.w;
        float rq = v0.x*v0.x+v0.y*v0.y+v0.z*v0.z+v0.w*v0.w
                 + v1.x*v1.x+v1.y*v1.y+v1.z*v1.z+v1.w*v1.w
                 + v2.x*v2.x+v2.y*v2.y+v2.z*v2.z+v2.w*v2.w
                 + v3.x*v3.x+v3.y*v3.y+v3.z*v3.z+v3.w*v3.w;
        cs0.x += v0.x; cs0.y += v0.y; cs0.z += v0.z; cs0.w += v0.w;
        cs1.x += v1.x; cs1.y += v1.y; cs1.z += v1.z; cs1.w += v1.w;
        cs2.x += v2.x; cs2.y += v2.y; cs2.z += v2.z; cs2.w += v2.w;
        cs3.x += v3.x; cs3.y += v3.y; cs3.z += v3.z; cs3.w += v3.w;
        #pragma unroll
        for (int off = 16; off; off >>= 1) {
            rs += __shfl_down_sync(0xffffffffu, rs, off);
            rq += __shfl_down_sync(0xffffffffu, rq, off);
        }
        if (lane == 0) { rowsum[t] = rs; rowsumsq[t] = rq; }
    }
    {
        float4* cp = reinterpret_cast<float4*>(scratch + warp * 512);
        cp[lane] = cs0; cp[lane + 32] = cs1; cp[lane + 64] = cs2; cp[lane + 96] = cs3;
    }
    __syncthreads();

    float cacc1 = 0.0f, cacc2 = 0.0f;
    #pragma unroll
    for (int w0 = 0; w0 < 8; w0++) {
        cacc1 += scratch[w0 * 512 + tid];
        cacc2 += scratch[w0 * 512 + tid + 256];
    }
    {
        float p = cacc1 * cacc1 + cacc2 * cacc2;
        #pragma unroll
        for (int off = 16; off; off >>= 1) p += __shfl_down_sync(0xffffffffu, p, off);
        if (lane == 0) red[warp] = p;
    }
    __syncthreads();
    if (tid == 0) {
        float t = 0.0f;
        #pragma unroll
        for (int i = 0; i < 8; i++) t += red[i];
        ssq = t;
    }
    __syncthreads();
    {
        const float inv = 1.0f / fmaxf(sqrtf(ssq), 2.56e-10f);
        glo[tid]       = cacc1 * inv;
        glo[tid + 256] = cacc2 * inv;
    }
    __syncthreads();

    {
        const float4* glo4 = reinterpret_cast<const float4*>(glo);
        #pragma unroll 1
        for (int r = 0; r < 32; r++) {
            const int t = warp * 32 + r;
            const float4* row = reinterpret_cast<const float4*>(xb + t * DIMV);
            float d = 0.0f;
            #pragma unroll
            for (int q = 0; q < 4; q++) {
                float4 v = row[lane + 32 * q];
                float4 gg = glo4[lane + 32 * q];
                d += v.x * gg.x + v.y * gg.y + v.z * gg.z + v.w * gg.w;
            }
            #pragma unroll
            for (int off = 16; off; off >>= 1) d += __shfl_down_sync(0xffffffffu, d, off);
            if (lane == 0) {
                float nr = sqrtf(rowsumsq[t]);
                score[t] = d / fmaxf(nr, 1e-12f) + ca[(size_t)b * NTOK + t];
            }
        }
    }
    __syncthreads();

    {
        const float sc = score[tid];
        int rank = 0;
        #pragma unroll 4
        for (int j = 0; j < NTOK; j++) {
            float sj = score[j];
            rank += (sj > sc) || (sj == sc && j < tid);
        }
        const float mu  = rowsum[tid] * (1.0f / 512.0f);
        const float var = rowsumsq[tid] * (1.0f / 512.0f) - mu * mu;
        if (rank < NKEEP) {
            g_selidx[b * NKEEP + rank] = tid;
            g_mu[b * NKEEP + rank]     = mu;
            g_rinv[b * NKEEP + rank]   = rsqrtf(var + 1e-5f);
        } else {
            nonidx[rank - NKEEP] = tid;
            nscore[rank - NKEEP] = sc;
        }
    }
    __syncthreads();

    if (warp == 0) {
        float v0 = nscore[lane], v1 = nscore[lane + 32],
              v2 = nscore[lane + 64], v3 = nscore[lane + 96];
        float m = fmaxf(fmaxf(v0, v1), fmaxf(v2, v3));
        #pragma unroll
        for (int off = 16; off; off >>= 1) m = fmaxf(m, __shfl_xor_sync(0xffffffffu, m, off));
        float e0 = expf(v0 - m), e1 = expf(v1 - m), e2 = expf(v2 - m), e3 = expf(v3 - m);
        float su = e0 + e1 + e2 + e3;
        #pragma unroll
        for (int off = 16; off; off >>= 1) su += __shfl_xor_sync(0xffffffffu, su, off);
        const float inv = 1.0f / su;
        nw[lane] = e0 * inv; nw[lane + 32] = e1 * inv;
        nw[lane + 64] = e2 * inv; nw[lane + 96] = e3 * inv;
    }
    __syncthreads();

    // extra row (out row 51), depth-8 prefetch
    {
        float acc1 = 0.0f, acc2 = 0.0f;
        float av[8], bv[8];
        #pragma unroll
        for (int i = 0; i < 8; i++) {
            const int idx = nonidx[i];
            av[i] = xb[(size_t)idx * DIMV + tid];
            bv[i] = xb[(size_t)idx * DIMV + tid + 256];
        }
        #pragma unroll 8
        for (int k = 0; k < 128; k++) {
            float an = 0.0f, bn = 0.0f;
            if (k + 8 < 128) {
                const int in = nonidx[k + 8];
                an = xb[(size_t)in * DIMV + tid];
                bn = xb[(size_t)in * DIMV + tid + 256];
            }
            const float w = nw[k];
            acc1 += w * av[0]; acc2 += w * bv[0];
            #pragma unroll
            for (int i = 0; i < 7; i++) { av[i] = av[i+1]; bv[i] = bv[i+1]; }
            av[7] = an; bv[7] = bn;
        }
        ob[51 * DIMV + tid]       = acc1;
        ob[51 * DIMV + tid + 256] = acc2;
    }
}

// =====================================================================
// K3: pipelined GEMM1(+LN+gelu) -> GEMM2 -> softmax -> aggr
//     grid = NB/2; each CTA processes 2 consecutive batches
// =====================================================================
#define ATS 129
#define A_OFF(buf) ((buf) * 4128)
#define B_OFF(buf) (8256 + (buf) * 3328)

struct __align__(16) SmemK3 {
    union {
        float st[14912];           // 59.6 KB: double-buffered A_T + Bt
        float H[128 * HST];        // 54.3 KB gelu out; cols 52..103 reused for w
    } u;
    float W2s[HID * 52];           // col 51 zero
    float g[512];
    float bln[512];
    float mu[128];
    float rinv[128];
    float b1p[104];
    float b2s[52];
    int   selidx[128];
};

__global__ __launch_bounds__(256, 2)
void k3_mlp(const float* __restrict__ x,
            const float* __restrict__ lng, const float* __restrict__ lnb,
            const float* __restrict__ W1, const float* __restrict__ b1,
            const float* __restrict__ W2, const float* __restrict__ b2,
            const float* __restrict__ scale, float* __restrict__ out)
{
    extern __shared__ char smem_raw[];
    SmemK3& s = *reinterpret_cast<SmemK3*>(smem_raw);

    const int tid = threadIdx.x, warp = tid >> 5, lane = tid & 31;

    // ---- per-launch constants (loaded once for both batches) ----
    s.g[tid]         = lng[tid];
    s.g[tid + 256]   = lng[tid + 256];
    s.bln[tid]       = lnb[tid];
    s.bln[tid + 256] = lnb[tid + 256];
    if (tid < 104) s.b1p[tid] = (tid < HID) ? b1[tid] : 0.0f;
    if (tid < KP)  s.b2s[tid] = b2[tid];
    if (tid < HID) s.W2s[tid * 52 + 51] = 0.0f;
    #pragma unroll
    for (int j = tid; j < HID * KP; j += 256)
        s.W2s[(j / KP) * 52 + (j % KP)] = W2[j];

    const int rg = warp >> 2;
    const int cg = warp & 3;
    const int r0 = rg * 64 + lane;
    const int c0 = cg * 26;
    const int tA = tid >> 1;
    const int k0 = (tid & 1) * 16;
    const uint32_t stB = smem_u32(s.u.st);
    const float sv = scale[0];

    #pragma unroll 1
    for (int bb = 0; bb < 2; bb++) {
        const int b = blockIdx.x * 2 + bb;
        const float* __restrict__ xb = x + (size_t)b * NTOK * DIMV;
        float* __restrict__ ob = out + (size_t)b * OUTROWS * DIMV;

        // per-batch selection state
        if (tid < 128) {
            s.selidx[tid] = g_selidx[b * NKEEP + tid];
            s.mu[tid]     = g_mu[b * NKEEP + tid];
            s.rinv[tid]   = g_rinv[b * NKEEP + tid];
        }
        // zero pad columns 102/103 of both B buffers (st overlaps H from previous batch)
        if (tid < 128) {
            const int buf = tid >> 6, rr = tid & 63, dk = rr >> 1, col = 102 + (rr & 1);
            s.u.st[B_OFF(buf) + dk * 104 + col] = 0.0f;
        }
        __syncthreads();

        const int rowi = s.selidx[tA];
        const float muv = s.mu[tA], ri = s.rinv[tA];
        const float* __restrict__ xrow = xb + (size_t)rowi * DIMV;

        ull acc0[13], acc1[13];
        #pragma unroll
        for (int i = 0; i < 13; i++) { acc0[i] = 0ull; acc1[i] = 0ull; }

        float4 a_r[4];

        // prologue: tile 0 into buf 0
        #pragma unroll
        for (int q = 0; q < 4; q++)
            a_r[q] = *reinterpret_cast<const float4*>(xrow + k0 + 4 * q);
        {
            const float* wsrc = W1;
            #pragma unroll
            for (int i = 0; i < 7; i++) {
                const int jj = tid + i * 256;
                if (jj < 1632) {
                    const int dk = jj / 51, c2 = jj - dk * 51;
                    CP_ASYNC8(stB + (uint32_t)(B_OFF(0) + dk * 104 + 2 * c2) * 4u,
                              wsrc + (size_t)dk * HID + 2 * c2);
                }
            }
            CP_COMMIT();
        }
        {
            #pragma unroll
            for (int q = 0; q < 4; q++) {
                float4 v = a_r[q];
                const int dd = k0 + 4 * q;
                float y0 = (v.x - muv) * ri * s.g[dd+0] + s.bln[dd+0];
                float y1 = (v.y - muv) * ri * s.g[dd+1] + s.bln[dd+1];
                float y2 = (v.z - muv) * ri * s.g[dd+2] + s.bln[dd+2];
                float y3 = (v.w - muv) * ri * s.g[dd+3] + s.bln[dd+3];
                float* ab = s.u.st + A_OFF(0);
                ab[(dd + 0) * ATS + tA] = y0;
                ab[(dd + 1) * ATS + tA] = y1;
                ab[(dd + 2) * ATS + tA] = y2;
                ab[(dd + 3) * ATS + tA] = y3;
            }
        }
        CP_WAIT0();
        __syncthreads();

        #pragma unroll 1
        for (int kt = 0; kt < 16; kt++) {
            const int buf = kt & 1;
            const int nbuf = buf ^ 1;
            const int dn0 = (kt + 1) * 32;

            if (kt < 15) {
                #pragma unroll
                for (int q = 0; q < 4; q++)
                    a_r[q] = *reinterpret_cast<const float4*>(xrow + dn0 + k0 + 4 * q);
                const float* wsrc = W1 + (size_t)dn0 * HID;
                #pragma unroll
                for (int i = 0; i < 7; i++) {
                    const int jj = tid + i * 256;
                    if (jj < 1632) {
                        const int dk = jj / 51, c2 = jj - dk * 51;
                        CP_ASYNC8(stB + (uint32_t)(B_OFF(nbuf) + dk * 104 + 2 * c2) * 4u,
                                  wsrc + (size_t)dk * HID + 2 * c2);
                    }
                }
                CP_COMMIT();
            }

            {
                const float* Abase = s.u.st + A_OFF(buf);
                const float* Bbase = s.u.st + B_OFF(buf);
                #pragma unroll 2
                for (int dk = 0; dk < 32; dk++) {
                    const float a0 = Abase[dk * ATS + r0];
                    const float a1 = Abase[dk * ATS + r0 + 32];
                    const ull a2_0 = pack2(a0, a0);
                    const ull a2_1 = pack2(a1, a1);
                    const ull* bp = reinterpret_cast<const ull*>(&Bbase[dk * 104 + c0]);
                    #pragma unroll
                    for (int i = 0; i < 13; i++) {
                        const ull bv = bp[i];
                        acc0[i] = ffma2(a2_0, bv, acc0[i]);
                        acc1[i] = ffma2(a2_1, bv, acc1[i]);
                    }
                }
            }

            if (kt < 15) {
                #pragma unroll
                for (int q = 0; q < 4; q++) {
                    float4 v = a_r[q];
                    const int dd = dn0 + k0 + 4 * q;
                    const int dl = k0 + 4 * q;
                    float y0 = (v.x - muv) * ri * s.g[dd+0] + s.bln[dd+0];
                    float y1 = (v.y - muv) * ri * s.g[dd+1] + s.bln[dd+1];
                    float y2 = (v.z - muv) * ri * s.g[dd+2] + s.bln[dd+2];
                    float y3 = (v.w - muv) * ri * s.g[dd+3] + s.bln[dd+3];
                    float* ab = s.u.st + A_OFF(nbuf);
                    ab[(dl + 0) * ATS + tA] = y0;
                    ab[(dl + 1) * ATS + tA] = y1;
                    ab[(dl + 2) * ATS + tA] = y2;
                    ab[(dl + 3) * ATS + tA] = y3;
                }
                CP_WAIT0();
            }
            __syncthreads();
        }

        // epilogue: H = gelu(acc + b1)
        {
            #pragma unroll
            for (int i = 0; i < 13; i++) {
                const int c = c0 + 2 * i;
                float2 p0 = unpack2(acc0[i]);
                float2 p1 = unpack2(acc1[i]);
                float bb0 = s.b1p[c], bb1 = s.b1p[c + 1];
                *reinterpret_cast<float2*>(&s.u.H[r0 * HST + c]) =
                    make_float2(gelu_exact(p0.x + bb0), gelu_exact(p0.y + bb1));
                *reinterpret_cast<float2*>(&s.u.H[(r0 + 32) * HST + c]) =
                    make_float2(gelu_exact(p1.x + bb0), gelu_exact(p1.y + bb1));
            }
        }
        __syncthreads();

        // ---- GEMM2 ----
        {
            const int t  = tid >> 1;
            const int cc0 = (tid & 1) * 26;
            ull accw[13];
            #pragma unroll
            for (int i = 0; i < 13; i++) accw[i] = 0ull;
            const float* hrow = &s.u.H[t * HST];
            #pragma unroll 2
            for (int k = 0; k < HID; k++) {
                const float h = hrow[k];
                const ull h2 = pack2(h, h);
                const ull* wr = reinterpret_cast<const ull*>(&s.W2s[k * 52 + cc0]);
                #pragma unroll
                for (int i = 0; i < 13; i++) accw[i] = ffma2(h2, wr[i], accw[i]);
            }
            __syncwarp();  // partner thread must finish reading hrow
            float* wrow = &s.u.H[t * HST + 52];
            #pragma unroll
            for (int i = 0; i < 13; i++) {
                float2 v = unpack2(accw[i]);
                const int c = cc0 + 2 * i;
                float o0 = (v.x + s.b2s[c]) * sv;
                float o1 = (c + 1 < KP) ? (v.y + s.b2s[c + 1]) * sv : 0.0f;
                *reinterpret_cast<float2*>(&wrow[c]) = make_float2(o0, o1);
            }
        }
        __syncthreads();

        // ---- softmax per weight column ----
        for (int c = warp; c < KP; c += 8) {
            const int base = 52 + c;
            float v0 = s.u.H[(lane) * HST + base],      v1 = s.u.H[(lane + 32) * HST + base],
                  v2 = s.u.H[(lane + 64) * HST + base], v3 = s.u.H[(lane + 96) * HST + base];
            float m = fmaxf(fmaxf(v0, v1), fmaxf(v2, v3));
            #pragma unroll
            for (int off = 16; off; off >>= 1) m = fmaxf(m, __shfl_xor_sync(0xffffffffu, m, off));
            float e0 = expf(v0 - m), e1 = expf(v1 - m), e2 = expf(v2 - m), e3 = expf(v3 - m);
            float su = e0 + e1 + e2 + e3;
            #pragma unroll
            for (int off = 16; off; off >>= 1) su += __shfl_xor_sync(0xffffffffu, su, off);
            const float inv = 1.0f / su;
            s.u.H[(lane) * HST + base]      = e0 * inv;
            s.u.H[(lane + 32) * HST + base] = e1 * inv;
            s.u.H[(lane + 64) * HST + base] = e2 * inv;
            s.u.H[(lane + 96) * HST + base] = e3 * inv;
        }
        __syncthreads();

        // ---- aggr: 2 p-halves, both columns per thread, depth-8 prefetch ----
        #pragma unroll 1
        for (int ph = 0; ph < 2; ph++) {
            const int pw = ph * 13;     // ull offset into w row
            const int cA = tid, cB = tid + 256;
            ull accA[13], accB[13];
            #pragma unroll
            for (int p = 0; p < 13; p++) { accA[p] = 0ull; accB[p] = 0ull; }
            float xa[8], xbv[8];
            #pragma unroll
            for (int i = 0; i < 8; i++) {
                const size_t ro = (size_t)s.selidx[i] * DIMV;
                xa[i]  = xb[ro + cA];
                xbv[i] = xb[ro + cB];
            }
            #pragma unroll 8
            for (int k = 0; k < 128; k++) {
                float na = 0.0f, nb = 0.0f;
                if (k + 8 < 128) {
                    const size_t ro = (size_t)s.selidx[k + 8] * DIMV;
                    na = xb[ro + cA];
                    nb = xb[ro + cB];
                }
                const ull x2a = pack2(xa[0], xa[0]);
                const ull x2b = pack2(xbv[0], xbv[0]);
                const ull* wr = reinterpret_cast<const ull*>(&s.u.H[k * HST + 52]) + pw;
                #pragma unroll
                for (int p = 0; p < 13; p++) {
                    const ull wv = wr[p];
                    accA[p] = ffma2(x2a, wv, accA[p]);
                    accB[p] = ffma2(x2b, wv, accB[p]);
                }
                #pragma unroll
                for (int i = 0; i < 7; i++) { xa[i] = xa[i+1]; xbv[i] = xbv[i+1]; }
                xa[7] = na; xbv[7] = nb;
            }
            #pragma unroll
            for (int p = 0; p < 13; p++) {
                const int pp = 2 * (pw + p);
                float2 vA = unpack2(accA[p]);
                float2 vB = unpack2(accB[p]);
                ob[pp * DIMV + cA] = vA.x;
                ob[pp * DIMV + cB] = vB.x;
                if (pp + 1 < KP) {
                    ob[(pp + 1) * DIMV + cA] = vA.y;
                    ob[(pp + 1) * DIMV + cB] = vB.y;
                }
            }
        }
        __syncthreads();  // H must be fully consumed before next batch reuses st
    }
}

extern "C" void kernel_launch(void* const* d_in, const int* in_sizes, int n_in,
                              void* d_out, int out_size) {
    (void)in_sizes; (void)n_in; (void)out_size;
    const float* x    = (const float*)d_in[0];
    const float* ca   = (const float*)d_in[1];
    const float* lng  = (const float*)d_in[2];
    const float* lnb  = (const float*)d_in[3];
    const float* W1   = (const float*)d_in[4];
    const float* b1   = (const float*)d_in[5];
    const float* W2   = (const float*)d_in[6];
    const float* b2   = (const float*)d_in[7];
    const float* sc   = (const float*)d_in[8];
    float* out = (float*)d_out;

    static_assert(sizeof(SmemK3) <= 113 * 1024, "K3 smem too big for 2 CTAs/SM");
    cudaFuncSetAttribute(k3_mlp, cudaFuncAttributeMaxDynamicSharedMemorySize,
                         (int)sizeof(SmemK3));
    k12_select<<<NB, 256>>>(x, ca, out);
    k3_mlp<<<NB / 2, 256, sizeof(SmemK3)>>>(x, lng, lnb, W1, b1, W2, b2, sc, out);
}

// round 17
// speedup vs baseline: 1.0393x; 1.0393x over previous
#include <cuda_runtime.h>
#include <cstdint>

#define DIMV   512
#define NTOK   256
#define NKEEP  128
#define HID    102
#define KP     51
#define OUTROWS 52
#define NB     512
#define HST    106   // H row stride: conflict-free GEMM2 row reads; even -> ull-aligned w

typedef unsigned long long ull;

__device__ int   g_selidx[NB * NKEEP];
__device__ float g_mu[NB * NKEEP];
__device__ float g_rinv[NB * NKEEP];

__device__ __forceinline__ ull ffma2(ull a, ull b, ull c) {
    ull d; asm("fma.rn.f32x2 %0, %1, %2, %3;" : "=l"(d) : "l"(a), "l"(b), "l"(c)); return d;
}
__device__ __forceinline__ ull pack2(float x, float y) {
    ull d; asm("mov.b64 %0, {%1, %2};" : "=l"(d) : "f"(x), "f"(y)); return d;
}
__device__ __forceinline__ float2 unpack2(ull v) {
    float2 r; asm("mov.b64 {%0, %1}, %2;" : "=f"(r.x), "=f"(r.y) : "l"(v)); return r;
}
__device__ __forceinline__ float gelu_exact(float v) {
    return 0.5f * v * (1.0f + erff(v * 0.70710678118654752f));
}
__device__ __forceinline__ uint32_t smem_u32(const void* p) {
    uint32_t a; asm("{ .reg .u64 t; cvta.to.shared.u64 t, %1; cvt.u32.u64 %0, t; }" : "=r"(a) : "l"(p)); return a;
}
#define CP_ASYNC8(dst, src) \
    asm volatile("cp.async.ca.shared.global [%0], [%1], 8;" :: "r"(dst), "l"(src) : "memory")
#define CP_COMMIT() asm volatile("cp.async.commit_group;" ::: "memory")
#define CP_WAIT0()  asm volatile("cp.async.wait_group 0;" ::: "memory")

// =====================================================================
// K12: stats + scores + partition + non-kept softmax + extra output row
// =====================================================================
__global__ __launch_bounds__(256)
void k12_select(const float* __restrict__ x, const float* __restrict__ ca,
                float* __restrict__ out)
{
    __shared__ float scratch[8 * 512];
    __shared__ float glo[512];
    __shared__ float rowsum[256];
    __shared__ float rowsumsq[256];
    __shared__ float score[256];
    __shared__ float nscore[128];
    __shared__ float nw[128];
    __shared__ int   nonidx[128];
    __shared__ float red[8];
    __shared__ float ssq;

    const int b = blockIdx.x, tid = threadIdx.x, warp = tid >> 5, lane = tid & 31;
    const float* __restrict__ xb = x + (size_t)b * NTOK * DIMV;
    float* __restrict__ ob = out + (size_t)b * OUTROWS * DIMV;

    float4 cs0 = make_float4(0,0,0,0), cs1 = cs0, cs2 = cs0, cs3 = cs0;
    #pragma unroll 1
    for (int r = 0; r < 32; r++) {
        const int t = warp * 32 + r;
        const float4* row = reinterpret_cast<const float4*>(xb + t * DIMV);
        float4 v0 = row[lane], v1 = row[lane + 32], v2 = row[lane + 64], v3 = row[lane + 96];
        float rs = v0.x+v0.y+v0.z+v0.w + v1.x+v1.y+v1.z+v1.w
                 + v2.x+v2.y+v2.z+v2.w + v3.x+v3.y+v3.z+v3.w;
        float rq = v0.x*v0.x+v0.y*v0.y+v0.z*v0.z+v0.w*v0.w
                 + v1.x*v1.x+v1.y*v1.y+v1.z*v1.z+v1.w*v1.w
                 + v2.x*v2.x+v2.y*v2.y+v2.z*v2.z+v2.w*v2.w
                 + v3.x*v3.x+v3.y*v3.y+v3.z*v3.z+v3.w*v3.w;
        cs0.x += v0.x; cs0.y += v0.y; cs0.z += v0.z; cs0.w += v0.w;
        cs1.x += v1.x; cs1.y += v1.y; cs1.z += v1.z; cs1.w += v1.w;
        cs2.x += v2.x; cs2.y += v2.y; cs2.z += v2.z; cs2.w += v2.w;
        cs3.x += v3.x; cs3.y += v3.y; cs3.z += v3.z; cs3.w += v3.w;
        #pragma unroll
        for (int off = 16; off; off >>= 1) {
            rs += __shfl_down_sync(0xffffffffu, rs, off);
            rq += __shfl_down_sync(0xffffffffu, rq, off);
        }
        if (lane == 0) { rowsum[t] = rs; rowsumsq[t] = rq; }
    }
    {
        float4* cp = reinterpret_cast<float4*>(scratch + warp * 512);
        cp[lane] = cs0; cp[lane + 32] = cs1; cp[lane + 64] = cs2; cp[lane + 96] = cs3;
    }
    __syncthreads();

    float cacc1 = 0.0f, cacc2 = 0.0f;
    #pragma unroll
    for (int w0 = 0; w0 < 8; w0++) {
        cacc1 += scratch[w0 * 512 + tid];
        cacc2 += scratch[w0 * 512 + tid + 256];
    }
    {
        float p = cacc1 * cacc1 + cacc2 * cacc2;
        #pragma unroll
        for (int off = 16; off; off >>= 1) p += __shfl_down_sync(0xffffffffu, p, off);
        if (lane == 0) red[warp] = p;
    }
    __syncthreads();
    if (tid == 0) {
        float t = 0.0f;
        #pragma unroll
        for (int i = 0; i < 8; i++) t += red[i];
        ssq = t;
    }
    __syncthreads();
    {
        const float inv = 1.0f / fmaxf(sqrtf(ssq), 2.56e-10f);
        glo[tid]       = cacc1 * inv;
        glo[tid + 256] = cacc2 * inv;
    }
    __syncthreads();

    {
        const float4* glo4 = reinterpret_cast<const float4*>(glo);
        #pragma unroll 1
        for (int r = 0; r < 32; r++) {
            const int t = warp * 32 + r;
            const float4* row = reinterpret_cast<const float4*>(xb + t * DIMV);
            float d = 0.0f;
            #pragma unroll
            for (int q = 0; q < 4; q++) {
                float4 v = row[lane + 32 * q];
                float4 gg = glo4[lane + 32 * q];
                d += v.x * gg.x + v.y * gg.y + v.z * gg.z + v.w * gg.w;
            }
            #pragma unroll
            for (int off = 16; off; off >>= 1) d += __shfl_down_sync(0xffffffffu, d, off);
            if (lane == 0) {
                float nr = sqrtf(rowsumsq[t]);
                score[t] = d / fmaxf(nr, 1e-12f) + ca[(size_t)b * NTOK + t];
            }
        }
    }
    __syncthreads();

    {
        const float sc = score[tid];
        int rank = 0;
        #pragma unroll 4
        for (int j = 0; j < NTOK; j++) {
            float sj = score[j];
            rank += (sj > sc) || (sj == sc && j < tid);
        }
        const float mu  = rowsum[tid] * (1.0f / 512.0f);
        const float var = rowsumsq[tid] * (1.0f / 512.0f) - mu * mu;
        if (rank < NKEEP) {
            g_selidx[b * NKEEP + rank] = tid;
            g_mu[b * NKEEP + rank]     = mu;
            g_rinv[b * NKEEP + rank]   = rsqrtf(var + 1e-5f);
        } else {
            nonidx[rank - NKEEP] = tid;
            nscore[rank - NKEEP] = sc;
        }
    }
    __syncthreads();

    if (warp == 0) {
        float v0 = nscore[lane], v1 = nscore[lane + 32],
              v2 = nscore[lane + 64], v3 = nscore[lane + 96];
        float m = fmaxf(fmaxf(v0, v1), fmaxf(v2, v3));
        #pragma unroll
        for (int off = 16; off; off >>= 1) m = fmaxf(m, __shfl_xor_sync(0xffffffffu, m, off));
        float e0 = expf(v0 - m), e1 = expf(v1 - m), e2 = expf(v2 - m), e3 = expf(v3 - m);
        float su = e0 + e1 + e2 + e3;
        #pragma unroll
        for (int off = 16; off; off >>= 1) su += __shfl_xor_sync(0xffffffffu, su, off);
        const float inv = 1.0f / su;
        nw[lane] = e0 * inv; nw[lane + 32] = e1 * inv;
        nw[lane + 64] = e2 * inv; nw[lane + 96] = e3 * inv;
    }
    __syncthreads();

    // extra row (out row 51), depth-8 prefetch
    {
        float acc1 = 0.0f, acc2 = 0.0f;
        float av[8], bv[8];
        #pragma unroll
        for (int i = 0; i < 8; i++) {
            const int idx = nonidx[i];
            av[i] = xb[(size_t)idx * DIMV + tid];
            bv[i] = xb[(size_t)idx * DIMV + tid + 256];
        }
        #pragma unroll 8
        for (int k = 0; k < 128; k++) {
            float an = 0.0f, bn = 0.0f;
            if (k + 8 < 128) {
                const int in = nonidx[k + 8];
                an = xb[(size_t)in * DIMV + tid];
                bn = xb[(size_t)in * DIMV + tid + 256];
            }
            const float w = nw[k];
            acc1 += w * av[0]; acc2 += w * bv[0];
            #pragma unroll
            for (int i = 0; i < 7; i++) { av[i] = av[i+1]; bv[i] = bv[i+1]; }
            av[7] = an; bv[7] = bn;
        }
        ob[51 * DIMV + tid]       = acc1;
        ob[51 * DIMV + tid + 256] = acc2;
    }
}

// =====================================================================
// K3: pipelined GEMM1(+LN+gelu) -> GEMM2 -> softmax -> aggr
//     grid = NB/2; each CTA processes 2 consecutive batches
// =====================================================================
#define ATS 129
#define A_OFF(buf) ((buf) * 4128)
#define B_OFF(buf) (8256 + (buf) * 3328)

struct __align__(16) SmemK3 {
    union {
        float st[14912];           // 59.6 KB: double-buffered A_T + Bt
        float H[128 * HST];        // 54.3 KB gelu out; cols 52..103 reused for w
    } u;
    float W2s[HID * 52];           // col 51 zero
    float g[512];
    float bln[512];
    float mu[128];
    float rinv[128];
    float b1p[104];
    float b2s[52];
    int   selidx[128];
};

__global__ __launch_bounds__(256, 2)
void k3_mlp(const float* __restrict__ x,
            const float* __restrict__ lng, const float* __restrict__ lnb,
            const float* __restrict__ W1, const float* __restrict__ b1,
            const float* __restrict__ W2, const float* __restrict__ b2,
            const float* __restrict__ scale, float* __restrict__ out)
{
    extern __shared__ char smem_raw[];
    SmemK3& s = *reinterpret_cast<SmemK3*>(smem_raw);

    const int tid = threadIdx.x, warp = tid >> 5, lane = tid & 31;

    // ---- per-launch constants (loaded once for both batches) ----
    s.g[tid]         = lng[tid];
    s.g[tid + 256]   = lng[tid + 256];
    s.bln[tid]       = lnb[tid];
    s.bln[tid + 256] = lnb[tid + 256];
    if (tid < 104) s.b1p[tid] = (tid < HID) ? b1[tid] : 0.0f;
    if (tid < KP)  s.b2s[tid] = b2[tid];
    if (tid < HID) s.W2s[tid * 52 + 51] = 0.0f;
    #pragma unroll
    for (int j = tid; j < HID * KP; j += 256)
        s.W2s[(j / KP) * 52 + (j % KP)] = W2[j];

    const int rg = warp >> 2;
    const int cg = warp & 3;
    const int r0 = rg * 64 + lane;
    const int c0 = cg * 26;
    const int tA = tid >> 1;
    const int k0 = (tid & 1) * 16;
    const uint32_t stB = smem_u32(s.u.st);
    const float sv = scale[0];

    #pragma unroll 1
    for (int bb = 0; bb < 2; bb++) {
        const int b = blockIdx.x * 2 + bb;
        const float* __restrict__ xb = x + (size_t)b * NTOK * DIMV;
        float* __restrict__ ob = out + (size_t)b * OUTROWS * DIMV;

        // per-batch selection state
        if (tid < 128) {
            s.selidx[tid] = g_selidx[b * NKEEP + tid];
            s.mu[tid]     = g_mu[b * NKEEP + tid];
            s.rinv[tid]   = g_rinv[b * NKEEP + tid];
        }
        // zero pad columns 102/103 of both B buffers (st overlaps H from previous batch)
        if (tid < 128) {
            const int buf = tid >> 6, rr = tid & 63, dk = rr >> 1, col = 102 + (rr & 1);
            s.u.st[B_OFF(buf) + dk * 104 + col] = 0.0f;
        }
        __syncthreads();

        const int rowi = s.selidx[tA];
        const float muv = s.mu[tA], ri = s.rinv[tA];
        const float* __restrict__ xrow = xb + (size_t)rowi * DIMV;

        ull acc0[13], acc1[13];
        #pragma unroll
        for (int i = 0; i < 13; i++) { acc0[i] = 0ull; acc1[i] = 0ull; }

        float4 a_r[4];

        // prologue: tile 0 into buf 0
        #pragma unroll
        for (int q = 0; q < 4; q++)
            a_r[q] = *reinterpret_cast<const float4*>(xrow + k0 + 4 * q);
        {
            const float* wsrc = W1;
            #pragma unroll
            for (int i = 0; i < 7; i++) {
                const int jj = tid + i * 256;
                if (jj < 1632) {
                    const int dk = jj / 51, c2 = jj - dk * 51;
                    CP_ASYNC8(stB + (uint32_t)(B_OFF(0) + dk * 104 + 2 * c2) * 4u,
                              wsrc + (size_t)dk * HID + 2 * c2);
                }
            }
            CP_COMMIT();
        }
        {
            #pragma unroll
            for (int q = 0; q < 4; q++) {
                float4 v = a_r[q];
                const int dd = k0 + 4 * q;
                float y0 = (v.x - muv) * ri * s.g[dd+0] + s.bln[dd+0];
                float y1 = (v.y - muv) * ri * s.g[dd+1] + s.bln[dd+1];
                float y2 = (v.z - muv) * ri * s.g[dd+2] + s.bln[dd+2];
                float y3 = (v.w - muv) * ri * s.g[dd+3] + s.bln[dd+3];
                float* ab = s.u.st + A_OFF(0);
                ab[(dd + 0) * ATS + tA] = y0;
                ab[(dd + 1) * ATS + tA] = y1;
                ab[(dd + 2) * ATS + tA] = y2;
                ab[(dd + 3) * ATS + tA] = y3;
            }
        }
        CP_WAIT0();
        __syncthreads();

        #pragma unroll 1
        for (int kt = 0; kt < 16; kt++) {
            const int buf = kt & 1;
            const int nbuf = buf ^ 1;
            const int dn0 = (kt + 1) * 32;

            if (kt < 15) {
                #pragma unroll
                for (int q = 0; q < 4; q++)
                    a_r[q] = *reinterpret_cast<const float4*>(xrow + dn0 + k0 + 4 * q);
                const float* wsrc = W1 + (size_t)dn0 * HID;
                #pragma unroll
                for (int i = 0; i < 7; i++) {
                    const int jj = tid + i * 256;
                    if (jj < 1632) {
                        const int dk = jj / 51, c2 = jj - dk * 51;
                        CP_ASYNC8(stB + (uint32_t)(B_OFF(nbuf) + dk * 104 + 2 * c2) * 4u,
                                  wsrc + (size_t)dk * HID + 2 * c2);
                    }
                }
                CP_COMMIT();
            }

            {
                const float* Abase = s.u.st + A_OFF(buf);
                const float* Bbase = s.u.st + B_OFF(buf);
                #pragma unroll 4
                for (int dk = 0; dk < 32; dk++) {
                    const float a0 = Abase[dk * ATS + r0];
                    const float a1 = Abase[dk * ATS + r0 + 32];
                    const ull a2_0 = pack2(a0, a0);
                    const ull a2_1 = pack2(a1, a1);
                    const ull* bp = reinterpret_cast<const ull*>(&Bbase[dk * 104 + c0]);
                    #pragma unroll
                    for (int i = 0; i < 13; i++) {
                        const ull bv = bp[i];
                        acc0[i] = ffma2(a2_0, bv, acc0[i]);
                        acc1[i] = ffma2(a2_1, bv, acc1[i]);
                    }
                }
            }

            if (kt < 15) {
                #pragma unroll
                for (int q = 0; q < 4; q++) {
                    float4 v = a_r[q];
                    const int dd = dn0 + k0 + 4 * q;
                    const int dl = k0 + 4 * q;
                    float y0 = (v.x - muv) * ri * s.g[dd+0] + s.bln[dd+0];
                    float y1 = (v.y - muv) * ri * s.g[dd+1] + s.bln[dd+1];
                    float y2 = (v.z - muv) * ri * s.g[dd+2] + s.bln[dd+2];
                    float y3 = (v.w - muv) * ri * s.g[dd+3] + s.bln[dd+3];
                    float* ab = s.u.st + A_OFF(nbuf);
                    ab[(dl + 0) * ATS + tA] = y0;
                    ab[(dl + 1) * ATS + tA] = y1;
                    ab[(dl + 2) * ATS + tA] = y2;
                    ab[(dl + 3) * ATS + tA] = y3;
                }
                CP_WAIT0();
            }
            __syncthreads();
        }

        // epilogue: H = gelu(acc + b1)
        {
            #pragma unroll
            for (int i = 0; i < 13; i++) {
                const int c = c0 + 2 * i;
                float2 p0 = unpack2(acc0[i]);
                float2 p1 = unpack2(acc1[i]);
                float bb0 = s.b1p[c], bb1 = s.b1p[c + 1];
                *reinterpret_cast<float2*>(&s.u.H[r0 * HST + c]) =
                    make_float2(gelu_exact(p0.x + bb0), gelu_exact(p0.y + bb1));
                *reinterpret_cast<float2*>(&s.u.H[(r0 + 32) * HST + c]) =
                    make_float2(gelu_exact(p1.x + bb0), gelu_exact(p1.y + bb1));
            }
        }
        __syncthreads();

        // ---- GEMM2 ----
        {
            const int t  = tid >> 1;
            const int cc0 = (tid & 1) * 26;
            ull accw[13];
            #pragma unroll
            for (int i = 0; i < 13; i++) accw[i] = 0ull;
            const float* hrow = &s.u.H[t * HST];
            #pragma unroll 2
            for (int k = 0; k < HID; k++) {
                const float h = hrow[k];
                const ull h2 = pack2(h, h);
                const ull* wr = reinterpret_cast<const ull*>(&s.W2s[k * 52 + cc0]);
                #pragma unroll
                for (int i = 0; i < 13; i++) accw[i] = ffma2(h2, wr[i], accw[i]);
            }
            __syncwarp();  // partner thread must finish reading hrow
            float* wrow = &s.u.H[t * HST + 52];
            #pragma unroll
            for (int i = 0; i < 13; i++) {
                float2 v = unpack2(accw[i]);
                const int c = cc0 + 2 * i;
                float o0 = (v.x + s.b2s[c]) * sv;
                float o1 = (c + 1 < KP) ? (v.y + s.b2s[c + 1]) * sv : 0.0f;
                *reinterpret_cast<float2*>(&wrow[c]) = make_float2(o0, o1);
            }
        }
        __syncthreads();

        // ---- softmax per weight column ----
        for (int c = warp; c < KP; c += 8) {
            const int base = 52 + c;
            float v0 = s.u.H[(lane) * HST + base],      v1 = s.u.H[(lane + 32) * HST + base],
                  v2 = s.u.H[(lane + 64) * HST + base], v3 = s.u.H[(lane + 96) * HST + base];
            float m = fmaxf(fmaxf(v0, v1), fmaxf(v2, v3));
            #pragma unroll
            for (int off = 16; off; off >>= 1) m = fmaxf(m, __shfl_xor_sync(0xffffffffu, m, off));
            float e0 = expf(v0 - m), e1 = expf(v1 - m), e2 = expf(v2 - m), e3 = expf(v3 - m);
            float su = e0 + e1 + e2 + e3;
            #pragma unroll
            for (int off = 16; off; off >>= 1) su += __shfl_xor_sync(0xffffffffu, su, off);
            const float inv = 1.0f / su;
            s.u.H[(lane) * HST + base]      = e0 * inv;
            s.u.H[(lane + 32) * HST + base] = e1 * inv;
            s.u.H[(lane + 64) * HST + base] = e2 * inv;
            s.u.H[(lane + 96) * HST + base] = e3 * inv;
        }
        __syncthreads();

        // ---- aggr: out[p][c] = sum_k w[k][p] * sel[k][c], depth-8 prefetch ----
        #pragma unroll 1
        for (int pass = 0; pass < 2; pass++) {
            const int c = tid + pass * 256;
            ull acc2[26];
            #pragma unroll
            for (int p = 0; p < 26; p++) acc2[p] = 0ull;
            float xv[8];
            #pragma unroll
            for (int i = 0; i < 8; i++)
                xv[i] = xb[(size_t)s.selidx[i] * DIMV + c];
            #pragma unroll 4
            for (int k = 0; k < 128; k++) {
                float nxt = (k + 8 < 128) ? xb[(size_t)s.selidx[k + 8] * DIMV + c] : 0.0f;
                const ull x2 = pack2(xv[0], xv[0]);
                const ull* wr = reinterpret_cast<const ull*>(&s.u.H[k * HST + 52]);
                #pragma unroll
                for (int p = 0; p < 26; p++) acc2[p] = ffma2(x2, wr[p], acc2[p]);
                #pragma unroll
                for (int i = 0; i < 7; i++) xv[i] = xv[i + 1];
                xv[7] = nxt;
            }
            #pragma unroll
            for (int p = 0; p < 26; p++) {
                float2 v = unpack2(acc2[p]);
                ob[(2 * p) * DIMV + c] = v.x;
                if (2 * p + 1 < KP) ob[(2 * p + 1) * DIMV + c] = v.y;
            }
        }
        __syncthreads();  // H must be fully consumed before next batch reuses st
    }
}

extern "C" void kernel_launch(void* const* d_in, const int* in_sizes, int n_in,
                              void* d_out, int out_size) {
    (void)in_sizes; (void)n_in; (void)out_size;
    const float* x    = (const float*)d_in[0];
    const float* ca   = (const float*)d_in[1];
    const float* lng  = (const float*)d_in[2];
    const float* lnb  = (const float*)d_in[3];
    const float* W1   = (const float*)d_in[4];
    const float* b1   = (const float*)d_in[5];
    const float* W2   = (const float*)d_in[6];
    const float* b2   = (const float*)d_in[7];
    const float* sc   = (const float*)d_in[8];
    float* out = (float*)d_out;

    static_assert(sizeof(SmemK3) <= 113 * 1024, "K3 smem too big for 2 CTAs/SM");
    cudaFuncSetAttribute(k3_mlp, cudaFuncAttributeMaxDynamicSharedMemorySize,
                         (int)sizeof(SmemK3));
    k12_select<<<NB, 256>>>(x, ca, out);
    k3_mlp<<<NB / 2, 256, sizeof(SmemK3)>>>(x, lng, lnb, W1, b1, W2, b2, sc, out);
}